// round 2
// baseline (speedup 1.0000x reference)
#include <cuda_runtime.h>
#include <math.h>

// Problem constants (fixed by dataset)
#define D       272     // capsule feature dim
#define NC      19      // num classes
#define NCPAD   20      // padded classes (even -> f32x2 pairs)
#define KCH     16      // k per chunk (272 = 17*16)
#define NCHUNK  17
#define TROWS   128     // rows per block tile
#define SROW    20      // smem caps row stride in floats (pad 16->20: conflict-free LDS.128)
#define THREADS 256
#define MAXROWS 65536
#define MAXNI   4096

typedef unsigned long long u64;

// Scratch (no allocations allowed anywhere)
__device__ float g_proj[(size_t)MAXROWS * NCPAD];   // ~5.24 MB, L2-resident for pass 2
__device__ float g_Wpad[D * NCPAD];                 // zero-padded W
__device__ int   g_bound[MAXNI + 1];

// ---- packed f32x2 helpers (PTX-only; ptxas never auto-fuses) ----
__device__ __forceinline__ u64 pack2(float lo, float hi) {
    u64 r; asm("mov.b64 %0, {%1, %2};" : "=l"(r) : "f"(lo), "f"(hi)); return r;
}
__device__ __forceinline__ u64 fma2(u64 a, u64 b, u64 c) {
    u64 r; asm("fma.rn.f32x2 %0, %1, %2, %3;" : "=l"(r) : "l"(a), "l"(b), "l"(c)); return r;
}
__device__ __forceinline__ float2 unpack2(u64 v) {
    float2 f; asm("mov.b64 {%0, %1}, %2;" : "=f"(f.x), "=f"(f.y) : "l"(v)); return f;
}

// ============================================================
// Pre-pass: pad W [272,19] -> g_Wpad [272,20] (col 19 = 0)
// ============================================================
__global__ void wpad_kernel(const float* __restrict__ W) {
    int i = blockIdx.x * blockDim.x + threadIdx.x;
    if (i < D * NCPAD) {
        int k = i / NCPAD;
        int c = i - k * NCPAD;
        g_Wpad[i] = (c < NC) ? W[k * NC + c] : 0.0f;
    }
}

// ============================================================
// Pass 1: proj[row][c] = sum_k caps[row][k] * Wpad[k][c]
// grid 512 x 256 threads. Tile 128 rows.
// Thread: cg = tid&1 -> cols cg*10..+9 ; rg = tid>>1 -> one row.
// Row-major smem chunk (128 x 16, stride 20), register-double-buffered LDGs.
// ============================================================
__global__ void __launch_bounds__(THREADS) proj_kernel(const float* __restrict__ caps) {
    __shared__ __align__(16) float s_W[D * NCPAD];        // 21760 B
    __shared__ __align__(16) float s_caps[TROWS * SROW];  // 10240 B

    const int tid = threadIdx.x;
    const int rowbase = blockIdx.x * TROWS;

    // Stage padded W with float4 (1360 float4 / 256 thr)
    {
        const float4* ws = (const float4*)g_Wpad;
        float4* wd = (float4*)s_W;
        for (int i = tid; i < D * NCPAD / 4; i += THREADS) wd[i] = ws[i];
    }

    const int cg = tid & 1;
    const int rg = tid >> 1;
    const float* wbase = &s_W[cg * 10];

    // Staging coords: 512 float4 per chunk, 2 per thread
    const int q0 = tid, q1 = tid + THREADS;
    const int r0 = q0 >> 2, c40 = q0 & 3;
    const int r1 = q1 >> 2, c41 = q1 & 3;
    const float4* src0 = (const float4*)&caps[(size_t)(rowbase + r0) * D + c40 * 4];
    const float4* src1 = (const float4*)&caps[(size_t)(rowbase + r1) * D + c41 * 4];
    float4* dst0 = (float4*)&s_caps[r0 * SROW + c40 * 4];
    float4* dst1 = (float4*)&s_caps[r1 * SROW + c41 * 4];

    u64 acc[5] = {0ull, 0ull, 0ull, 0ull, 0ull};

    float4 p0 = src0[0];
    float4 p1 = src1[0];

#pragma unroll 1
    for (int kc = 0; kc < NCHUNK; ++kc) {
        __syncthreads();          // prior chunk's readers done (covers W staging at kc=0)
        *dst0 = p0;
        *dst1 = p1;
        __syncthreads();
        if (kc + 1 < NCHUNK) {    // prefetch next chunk: LDG latency overlaps compute
            p0 = src0[(kc + 1) * 4];
            p1 = src1[(kc + 1) * 4];
        }

        const float* wk = &wbase[kc * KCH * NCPAD];
        const float* ck = &s_caps[rg * SROW];
#pragma unroll
        for (int j4 = 0; j4 < 4; ++j4) {
            float4 a = *(const float4*)&ck[j4 * 4];
            const float* w0 = &wk[(j4 * 4) * NCPAD];
            u64 aa;
            aa = pack2(a.x, a.x);
#pragma unroll
            for (int u = 0; u < 5; ++u) acc[u] = fma2(aa, ((const u64*)&w0[0 * NCPAD])[u], acc[u]);
            aa = pack2(a.y, a.y);
#pragma unroll
            for (int u = 0; u < 5; ++u) acc[u] = fma2(aa, ((const u64*)&w0[1 * NCPAD])[u], acc[u]);
            aa = pack2(a.z, a.z);
#pragma unroll
            for (int u = 0; u < 5; ++u) acc[u] = fma2(aa, ((const u64*)&w0[2 * NCPAD])[u], acc[u]);
            aa = pack2(a.w, a.w);
#pragma unroll
            for (int u = 0; u < 5; ++u) acc[u] = fma2(aa, ((const u64*)&w0[3 * NCPAD])[u], acc[u]);
        }
    }

    // Writeback: row stride 20 floats, 8B-aligned pair stores
    float* op = &g_proj[(size_t)(rowbase + rg) * NCPAD + cg * 10];
#pragma unroll
    for (int u = 0; u < 5; ++u) {
        float2 f = unpack2(acc[u]);
        op[2 * u + 0] = f.x;
        op[2 * u + 1] = f.y;
    }
}

// ============================================================
// Segment boundaries from sorted segment_ids (handles empty segments).
// ============================================================
__global__ void bounds_kernel(const int* __restrict__ seg, int P, int NI) {
    int p = blockIdx.x * blockDim.x + threadIdx.x;
    if (p >= P) return;
    int cur  = seg[p];
    int prev = (p == 0) ? -1 : seg[p - 1];
    for (int s = prev + 1; s <= cur; ++s) g_bound[s] = p;
    if (p == P - 1) {
        for (int s = cur + 1; s <= NI; ++s) g_bound[s] = P;
    }
}

// ============================================================
// Pass 2: one warp per segment; lanes 0..19 own channels.
// ============================================================
__global__ void __launch_bounds__(256) pool_kernel(const int* __restrict__ point_idx,
                                                   const float* __restrict__ bias,
                                                   float* __restrict__ out, int NI) {
    int warp = (blockIdx.x * blockDim.x + threadIdx.x) >> 5;
    int lane = threadIdx.x & 31;
    if (warp >= NI) return;

    int start = g_bound[warp];
    int end   = g_bound[warp + 1];

    float a0 = 0.f, a1 = 0.f, a2 = 0.f, a3 = 0.f;
    if (lane < NCPAD) {
        const int c = lane;
        int p = start;
        for (; p + 4 <= end; p += 4) {
            int i0 = point_idx[p + 0];
            int i1 = point_idx[p + 1];
            int i2 = point_idx[p + 2];
            int i3 = point_idx[p + 3];
            a0 += g_proj[(size_t)i0 * NCPAD + c];
            a1 += g_proj[(size_t)i1 * NCPAD + c];
            a2 += g_proj[(size_t)i2 * NCPAD + c];
            a3 += g_proj[(size_t)i3 * NCPAD + c];
        }
        for (; p < end; ++p) a0 += g_proj[(size_t)point_idx[p] * NCPAD + c];
    }

    if (lane < NC) {
        float acc = (a0 + a1) + (a2 + a3);
        int cnt = end - start;
        float denom = (float)(cnt > 0 ? cnt : 1);
        float x = acc / denom + bias[lane];
        out[(size_t)warp * NC + lane] = 1.0f / (1.0f + expf(-x));
    }
}

// ============================================================
extern "C" void kernel_launch(void* const* d_in, const int* in_sizes, int n_in,
                              void* d_out, int out_size) {
    const float* caps = (const float*)d_in[0];   // [65536, 272]
    const float* Wm   = (const float*)d_in[1];   // [272, 19]
    const float* bias = (const float*)d_in[2];   // [19]
    const int*   pidx = (const int*)d_in[3];     // [P]
    const int*   seg  = (const int*)d_in[4];     // [P] sorted

    const int P     = in_sizes[3];
    const int NI    = out_size / NC;             // 4096
    const int nrows = in_sizes[0] / D;           // 65536

    wpad_kernel<<<(D * NCPAD + 255) / 256, 256>>>(Wm);
    proj_kernel<<<nrows / TROWS, THREADS>>>(caps);
    bounds_kernel<<<(P + 255) / 256, 256>>>(seg, P, NI);
    pool_kernel<<<(NI * 32 + 255) / 256, 256>>>(pidx, bias, (float*)d_out, NI);
}

// round 3
// speedup vs baseline: 1.0711x; 1.0711x over previous
#include <cuda_runtime.h>
#include <math.h>

// Problem constants (fixed by dataset)
#define D       272     // capsule feature dim
#define NC      19      // num classes
#define NCPAD   20      // padded classes in g_proj rows
#define WPAD    24      // padded W row: [cg][12], each 10-col group 16B-aligned
#define KCH     16      // k per chunk (272 = 17*16)
#define NCHUNK  17
#define TROWS   128     // rows per block tile
#define THREADS 128
#define STAGES  2
#define MAXROWS 65536
#define MAXNI   4096

typedef unsigned long long u64;

// Scratch (no allocations allowed anywhere)
__device__ float g_proj[(size_t)MAXROWS * NCPAD];   // ~5.24 MB
__device__ float g_Wpad[D * WPAD];                  // padded W
__device__ int   g_bound[MAXNI + 1];

// ---- packed f32x2 helpers (PTX-only) ----
__device__ __forceinline__ u64 pack2(float lo, float hi) {
    u64 r; asm("mov.b64 %0, {%1, %2};" : "=l"(r) : "f"(lo), "f"(hi)); return r;
}
__device__ __forceinline__ u64 fma2(u64 a, u64 b, u64 c) {
    u64 r; asm("fma.rn.f32x2 %0, %1, %2, %3;" : "=l"(r) : "l"(a), "l"(b), "l"(c)); return r;
}
__device__ __forceinline__ float2 unpack2(u64 v) {
    float2 f; asm("mov.b64 {%0, %1}, %2;" : "=f"(f.x), "=f"(f.y) : "l"(v)); return f;
}

// ---- cp.async helpers ----
__device__ __forceinline__ void cp_async16(void* sdst, const void* gsrc) {
    unsigned sa = (unsigned)__cvta_generic_to_shared(sdst);
    asm volatile("cp.async.ca.shared.global [%0], [%1], 16;\n" :: "r"(sa), "l"(gsrc));
}
__device__ __forceinline__ void cp_commit() {
    asm volatile("cp.async.commit_group;\n" ::: "memory");
}
template <int N>
__device__ __forceinline__ void cp_wait() {
    asm volatile("cp.async.wait_group %0;\n" :: "n"(N) : "memory");
}

union F4U2 { float4 f4; u64 u[2]; };
union F2U1 { float2 f2; u64 u; };

// ============================================================
// Pre-pass: W [272,19] -> g_Wpad [272][24]: cols cg*12+j = W[k][cg*10+j] (j<10), else 0
// ============================================================
__global__ void wpad_kernel(const float* __restrict__ W) {
    int i = blockIdx.x * blockDim.x + threadIdx.x;
    if (i < D * WPAD) {
        int k = i / WPAD;
        int j = i - k * WPAD;
        int cg = j / 12, jj = j - cg * 12;
        int c = cg * 10 + jj;
        g_Wpad[i] = (jj < 10 && c < NC) ? W[k * NC + c] : 0.0f;
    }
}

// ============================================================
// Pass 1: proj = caps @ Wpad.  cp.async 2-stage pipeline.
// grid 512 x 128 threads; tile 128 rows.
// Thread: cg = tid&1 (cols cg*10..+9), rg = tid>>1 -> rows rg, rg+64.
// smem caps chunk layout: [stage][c4][row] float4  (k-major, conflict-free)
// ============================================================
__global__ void __launch_bounds__(THREADS) proj_kernel(const float* __restrict__ caps) {
    __shared__ __align__(16) float  s_W[D * WPAD];              // 26112 B
    __shared__ __align__(16) float4 s_caps[STAGES][4][TROWS];   // 16384 B

    const int tid = threadIdx.x;
    const size_t rowbase = (size_t)blockIdx.x * TROWS;

    // Stage padded W via cp.async (part of group 0)
    {
        const float4* ws = (const float4*)g_Wpad;
        float4* wd = (float4*)s_W;
        for (int i = tid; i < D * WPAD / 4; i += THREADS)
            cp_async16(&wd[i], &ws[i]);
    }

    // chunk issuer: 512 x 16B per chunk, 4 per thread, coalesced by row groups
#define ISSUE_CHUNK(kc, stage)                                            \
    {                                                                     \
        _Pragma("unroll")                                                 \
        for (int i = 0; i < 4; ++i) {                                     \
            int q = tid + i * THREADS;                                    \
            int r = q >> 2, c4 = q & 3;                                   \
            cp_async16(&s_caps[stage][c4][r],                             \
                       &caps[(rowbase + r) * D + (kc) * KCH + c4 * 4]);   \
        }                                                                 \
    }

    ISSUE_CHUNK(0, 0); cp_commit();   // group0 = W + chunk0
    ISSUE_CHUNK(1, 1); cp_commit();   // group1 = chunk1

    const int cg = tid & 1;
    const int rg = tid >> 1;          // 0..63
    const int row0 = rg, row1 = rg + 64;
    const float* wb = &s_W[cg * 12];

    u64 acc0[5] = {0, 0, 0, 0, 0};
    u64 acc1[5] = {0, 0, 0, 0, 0};

#pragma unroll 1
    for (int kc = 0; kc < NCHUNK; ++kc) {
        if (kc < NCHUNK - 1) cp_wait<1>(); else cp_wait<0>();
        __syncthreads();                       // publish smem chunk to all threads
        const int st = kc & 1;

#pragma unroll
        for (int j4 = 0; j4 < 4; ++j4) {
            float4 a0 = s_caps[st][j4][row0];
            float4 a1 = s_caps[st][j4][row1];
            const float* wk = &wb[(kc * KCH + j4 * 4) * WPAD];
#pragma unroll
            for (int kk = 0; kk < 4; ++kk) {
                const float* w = &wk[kk * WPAD];
                F4U2 wA; wA.f4 = *(const float4*)(w);       // cols 0-3  (2 pairs)
                F4U2 wB; wB.f4 = *(const float4*)(w + 4);   // cols 4-7  (2 pairs)
                F2U1 wC; wC.f2 = *(const float2*)(w + 8);   // cols 8-9  (1 pair)
                float e0 = (kk == 0) ? a0.x : (kk == 1) ? a0.y : (kk == 2) ? a0.z : a0.w;
                float e1 = (kk == 0) ? a1.x : (kk == 1) ? a1.y : (kk == 2) ? a1.z : a1.w;
                u64 p0 = pack2(e0, e0);
                u64 p1 = pack2(e1, e1);
                acc0[0] = fma2(p0, wA.u[0], acc0[0]);
                acc0[1] = fma2(p0, wA.u[1], acc0[1]);
                acc0[2] = fma2(p0, wB.u[0], acc0[2]);
                acc0[3] = fma2(p0, wB.u[1], acc0[3]);
                acc0[4] = fma2(p0, wC.u,    acc0[4]);
                acc1[0] = fma2(p1, wA.u[0], acc1[0]);
                acc1[1] = fma2(p1, wA.u[1], acc1[1]);
                acc1[2] = fma2(p1, wB.u[0], acc1[2]);
                acc1[3] = fma2(p1, wB.u[1], acc1[3]);
                acc1[4] = fma2(p1, wC.u,    acc1[4]);
            }
        }

        __syncthreads();                       // all reads of stage st done
        if (kc + 2 < NCHUNK) { ISSUE_CHUNK(kc + 2, st); cp_commit(); }
    }

    // Writeback (8B-aligned float2 stores)
    float* op0 = &g_proj[(rowbase + row0) * NCPAD + cg * 10];
    float* op1 = &g_proj[(rowbase + row1) * NCPAD + cg * 10];
#pragma unroll
    for (int u = 0; u < 5; ++u) {
        *(float2*)&op0[2 * u] = unpack2(acc0[u]);
        *(float2*)&op1[2 * u] = unpack2(acc1[u]);
    }
#undef ISSUE_CHUNK
}

// ============================================================
// Segment boundaries from sorted segment_ids (handles empty segments).
// ============================================================
__global__ void bounds_kernel(const int* __restrict__ seg, int P, int NI) {
    int p = blockIdx.x * blockDim.x + threadIdx.x;
    if (p >= P) return;
    int cur  = seg[p];
    int prev = (p == 0) ? -1 : seg[p - 1];
    for (int s = prev + 1; s <= cur; ++s) g_bound[s] = p;
    if (p == P - 1) {
        for (int s = cur + 1; s <= NI; ++s) g_bound[s] = P;
    }
}

// ============================================================
// Pass 2: one warp per segment; lanes 0..19 own channels.
// ============================================================
__global__ void __launch_bounds__(256) pool_kernel(const int* __restrict__ point_idx,
                                                   const float* __restrict__ bias,
                                                   float* __restrict__ out, int NI) {
    int warp = (blockIdx.x * blockDim.x + threadIdx.x) >> 5;
    int lane = threadIdx.x & 31;
    if (warp >= NI) return;

    int start = g_bound[warp];
    int end   = g_bound[warp + 1];

    float a0 = 0.f, a1 = 0.f, a2 = 0.f, a3 = 0.f;
    if (lane < NCPAD) {
        const int c = lane;
        int p = start;
        for (; p + 4 <= end; p += 4) {
            int i0 = point_idx[p + 0];
            int i1 = point_idx[p + 1];
            int i2 = point_idx[p + 2];
            int i3 = point_idx[p + 3];
            a0 += g_proj[(size_t)i0 * NCPAD + c];
            a1 += g_proj[(size_t)i1 * NCPAD + c];
            a2 += g_proj[(size_t)i2 * NCPAD + c];
            a3 += g_proj[(size_t)i3 * NCPAD + c];
        }
        for (; p < end; ++p) a0 += g_proj[(size_t)point_idx[p] * NCPAD + c];
    }

    if (lane < NC) {
        float acc = (a0 + a1) + (a2 + a3);
        int cnt = end - start;
        float denom = (float)(cnt > 0 ? cnt : 1);
        float x = acc / denom + bias[lane];
        out[(size_t)warp * NC + lane] = 1.0f / (1.0f + expf(-x));
    }
}

// ============================================================
extern "C" void kernel_launch(void* const* d_in, const int* in_sizes, int n_in,
                              void* d_out, int out_size) {
    const float* caps = (const float*)d_in[0];   // [65536, 272]
    const float* Wm   = (const float*)d_in[1];   // [272, 19]
    const float* bias = (const float*)d_in[2];   // [19]
    const int*   pidx = (const int*)d_in[3];     // [P]
    const int*   seg  = (const int*)d_in[4];     // [P] sorted

    const int P     = in_sizes[3];
    const int NI    = out_size / NC;             // 4096
    const int nrows = in_sizes[0] / D;           // 65536

    wpad_kernel<<<(D * WPAD + 255) / 256, 256>>>(Wm);
    bounds_kernel<<<(P + 255) / 256, 256>>>(seg, P, NI);
    proj_kernel<<<nrows / TROWS, THREADS>>>(caps);
    pool_kernel<<<(NI * 32 + 255) / 256, 256>>>(pidx, bias, (float*)d_out, NI);
}